// round 3
// baseline (speedup 1.0000x reference)
#include <cuda_runtime.h>
#include <cstdint>

#define L_SEQ 1024
#define N_ST  256

// Output layout: concat of (c_all[L,N], y_all[L], GBT_A[L,N,N], GBT_B[L,N])
#define OFF_C  ((size_t)0)
#define OFF_Y  ((size_t)(L_SEQ * N_ST))
#define OFF_A  (OFF_Y + (size_t)L_SEQ)
#define OFF_B  (OFF_A + (size_t)L_SEQ * N_ST * N_ST)

// Per-k coefficient tables (natural state order), 3MB, L2-resident.
// [k][0][i] = g_i = s*r_i/e_i   [k][1][i] = h_i = 1/e_i   [k][2][i] = Bd_i*f_k
__device__ float g_tab[L_SEQ][3][N_ST];

// ---------------------------------------------------------------------------
// Tables + GBT_B.  Bd_i = ss*(r_i/e_i)*prod_{j<i}(1 - s*r_j^2/e_j).
// ---------------------------------------------------------------------------
__global__ void __launch_bounds__(N_ST) hippo_tabs(
        const float* __restrict__ f, const float* __restrict__ Bvec,
        float* __restrict__ out) {
    __shared__ float sc[2][N_ST];
    const int k = blockIdx.x, j = threadIdx.x;
    const float ss = 1.0f / (float)(k + 1);
    const float s  = 0.5f * ss;
    const float r  = Bvec[j];
    const float e  = fmaf(s, (float)(j + 1), 1.0f);
    const float h  = 1.0f / e;
    const float g  = s * r * h;
    const float al = fmaf(-r, g, 1.0f);

    int pb = 0;
    sc[0][j] = al;
    __syncthreads();
    #pragma unroll
    for (int off = 1; off < N_ST; off <<= 1) {
        float v = sc[pb][j];
        if (j >= off) v *= sc[pb][j - off];
        sc[pb ^ 1][j] = v;
        pb ^= 1;
        __syncthreads();
    }
    const float E  = (j == 0) ? 1.0f : sc[pb][j - 1];
    const float Bd = ss * r * h * E;

    g_tab[k][0][j] = g;
    g_tab[k][1][j] = h;
    g_tab[k][2][j] = Bd * f[k];
    out[OFF_B + (size_t)k * N_ST + j] = Bd;
}

// ---------------------------------------------------------------------------
// Fused kernel, 128-thread blocks.
//   block 0      : 128-stage systolic scan (4 warps, 2 states/lane)
//   blocks 1..L  : GBT_A fill for k = blockIdx.x-1 (2 columns/thread)
// ---------------------------------------------------------------------------
__global__ void __launch_bounds__(128) hippo_fused(
        const float* __restrict__ initS, const float* __restrict__ Bvec,
        float* __restrict__ out) {
    __shared__ float sm[2 * N_ST + 16];   // fillA: r_s|a_s ; scan: mailbox

    if (blockIdx.x != 0) {
        // ================= GBT_A fill =================
        float* r_s = sm;
        float* a_s = sm + N_ST;
        const int k = blockIdx.x - 1;
        const int t = threadIdx.x;
        #pragma unroll
        for (int idx = t; idx < N_ST; idx += 128) {
            r_s[idx] = Bvec[idx];
            a_s[idx] = g_tab[k][0][idx];        // a_i = s*r_i/e_i
        }
        __syncthreads();

        const int j0 = 2 * t, j1 = j0 + 1;
        const float inv0 = g_tab[k][1][j0];     // 1/e_j
        const float inv1 = g_tab[k][1][j1];
        float S0 = 0.0f, S1 = 0.0f;
        float* outA = out + OFF_A + (size_t)k * (N_ST * N_ST) + j0;

        #pragma unroll 4
        for (int i = 0; i < N_ST; i++) {
            const float a = a_s[i], r = r_s[i];
            float x0 = -a * S0; if (i == j0) x0 = inv0;
            float x1 = -a * S1; if (i == j1) x1 = inv1;
            S0 = fmaf(r, x0, S0);
            S1 = fmaf(r, x1, S1);
            const float v0 = 2.0f * x0 - ((i == j0) ? 1.0f : 0.0f);
            const float v1 = 2.0f * x1 - ((i == j1) ? 1.0f : 0.0f);
            *(float2*)(outA + (size_t)i * N_ST) = make_float2(v0, v1);
        }
        return;
    }

    // ================= Systolic scan =================
    // Stage g = threadIdx.x owns states {2g, 2g+1}; at tick t it runs time
    // step k = t - g, receiving (V, ys) of stage g-1 (same k, previous tick)
    // via shfl.up within a warp / smem mailbox across warps.
    float2* mbox = (float2*)(sm);               // [parity][warp]
    const int g    = threadIdx.x;
    const int w    = g >> 5;
    const int lane = g & 31;
    const int i0   = 2 * g;

    const float r0 = Bvec[i0], r1 = Bvec[i0 + 1];
    float c0 = initS[i0], c1 = initS[i0 + 1];

    float* outC = out + OFF_C;
    float* outY = out + OFF_Y;
    const float* tb = &g_tab[0][0][0];

    // Depth-4 register prefetch ring: 3 float2 per tick (g, h, b).
    float2 pf[4][3];
    auto pref = [&](int slot, int t) {
        int kk = t - g;
        kk = (kk < 0) ? 0 : (kk > L_SEQ - 1 ? L_SEQ - 1 : kk);
        const float* p = tb + (size_t)kk * (3 * N_ST) + i0;
        pf[slot][0] = *(const float2*)(p);
        pf[slot][1] = *(const float2*)(p + N_ST);
        pf[slot][2] = *(const float2*)(p + 2 * N_ST);
    };
    #pragma unroll
    for (int u = 0; u < 4; u++) pref(u, u);

    float V = 0.0f, ys = 0.0f;

    for (int t0 = 0; t0 < 1152; t0 += 4) {      // 1152 >= L_SEQ + 127
        #pragma unroll
        for (int u = 0; u < 4; u++) {
            const int t = t0 + u;
            __syncthreads();                    // tick boundary: orders mailbox
            float Vin = __shfl_up_sync(0xffffffffu, V, 1);
            float yin = __shfl_up_sync(0xffffffffu, ys, 1);
            if (lane == 0) {
                if (w == 0) { Vin = 0.0f; yin = 0.0f; }
                else {
                    float2 m = mbox[((t + 1) & 1) * 4 + (w - 1)];
                    Vin = m.x; yin = m.y;
                }
            }
            const int k = t - g;
            if ((unsigned)k < (unsigned)L_SEQ) {
                const float G0 = pf[u][0].x, G1 = pf[u][0].y;
                const float H0 = pf[u][1].x, H1 = pf[u][1].y;
                const float b0 = pf[u][2].x, b1 = pf[u][2].y;

                V = Vin;
                // state i0
                const float hc0 = H0 * c0;
                const float z0  = fmaf(-G0, V, hc0);
                const float al0 = fmaf(-r0, G0, 1.0f);
                V = fmaf(al0, V, r0 * hc0);
                const float cn0 = fmaf(2.0f, z0, b0 - c0);
                // state i0+1
                const float hc1 = H1 * c1;
                const float z1  = fmaf(-G1, V, hc1);
                const float al1 = fmaf(-r1, G1, 1.0f);
                V = fmaf(al1, V, r1 * hc1);
                const float cn1 = fmaf(2.0f, z1, b1 - c1);

                ys = yin + (cn0 + cn1);
                c0 = cn0; c1 = cn1;

                *(float2*)(outC + (size_t)k * N_ST + i0) = make_float2(cn0, cn1);
                if (g == 127) outY[k] = ys;
            } else {
                V = 0.0f; ys = 0.0f;
            }
            if (lane == 31) mbox[(t & 1) * 4 + w] = make_float2(V, ys);
            pref(u, t + 4);
        }
    }
}

// ---------------------------------------------------------------------------
extern "C" void kernel_launch(void* const* d_in, const int* in_sizes, int n_in,
                              void* d_out, int out_size) {
    const float* f    = (const float*)d_in[0];  // (L,1)
    const float* init = (const float*)d_in[1];  // (N,1)
    // d_in[2] = A (unused: closed form), d_in[3] = B (= r vector)
    const float* B    = (const float*)d_in[3];
    float* out = (float*)d_out;

    hippo_tabs<<<L_SEQ, N_ST>>>(f, B, out);
    hippo_fused<<<L_SEQ + 1, 128>>>(init, B, out);
}